// round 2
// baseline (speedup 1.0000x reference)
#include <cuda_runtime.h>
#include <cstdint>
#include <cstdio>

// Problem constants
#define BB 2
#define TT 2048
#define DD 1024
#define HH 16
#define DHH 64
#define MM (BB*TT)          // 4096 rows

// ---------------------------------------------------------------------------
// Scratch (device globals: no runtime allocation allowed)
// ---------------------------------------------------------------------------
__device__ float g_qc[MM*DD];          // x@Wq (pre-conv), [M,D]
__device__ float g_kc[MM*DD];
__device__ float g_vc[MM*DD];
__device__ float g_q [MM*DD];          // post conv/silu/l2norm, [B,H,T,DH]
__device__ float g_k [MM*DD];
__device__ float g_v [MM*DD];
__device__ float g_beta[BB*HH*TT];     // [B,H,T]
__device__ float g_o [MM*DD];          // scan output, [B,H,T,DH]
__device__ float g_on[MM*DD];          // rmsnormed + transposed, [M,D]

// ---------------------------------------------------------------------------
// f32x2 packed helpers (Blackwell FFMA2 — 2x fp32 throughput vs 3-reg FFMA)
// ---------------------------------------------------------------------------
__device__ __forceinline__ unsigned long long dup2(float x){
  unsigned long long r;
  unsigned u = __float_as_uint(x);
  asm("mov.b64 %0, {%1, %1};" : "=l"(r) : "r"(u));
  return r;
}
__device__ __forceinline__ void ffma2(unsigned long long &c, unsigned long long a, unsigned long long b){
  asm("fma.rn.f32x2 %0, %1, %2, %0;" : "+l"(c) : "l"(a), "l"(b));
}
__device__ __forceinline__ float2 unpk2(unsigned long long p){
  unsigned lo, hi;
  asm("mov.b64 {%0, %1}, %2;" : "=r"(lo), "=r"(hi) : "l"(p));
  return make_float2(__uint_as_float(lo), __uint_as_float(hi));
}

// ---------------------------------------------------------------------------
// GEMM: C[M,N] = A[M,K] @ B[K,N], fp32 in, fp32 out, f32x2 inner loop.
// 128x128 block tile, K-tile 16, 256 threads, 8x8 per thread (cols packed x2).
// M,N,K assumed multiples of tile sizes (4096/1024/1024 here).
// ---------------------------------------------------------------------------
#define GBM 128
#define GBN 128
#define GBK 16

__global__ __launch_bounds__(256, 2)
void gemm_f32x2_kernel(const float* __restrict__ A, const float* __restrict__ B,
                       float* __restrict__ C, int M, int N, int Kd)
{
  __shared__ __align__(16) unsigned long long As2[GBK][GBM + 2]; // A duplicated into pairs
  __shared__ __align__(16) float Bs[GBK][GBN + 4];

  const int tid   = threadIdx.x;
  const int r0    = (tid >> 4) * 8;    // 0..120
  const int c0    = (tid & 15) * 8;    // 0..120
  const int tileM = blockIdx.y * GBM;
  const int tileN = blockIdx.x * GBN;

  unsigned long long acc[8][4];
  #pragma unroll
  for (int r = 0; r < 8; r++)
    #pragma unroll
    for (int c = 0; c < 4; c++) acc[r][c] = 0ull;

  const float* Ab = A + (size_t)tileM * Kd;
  const float* Bb = B + tileN;

  for (int kt = 0; kt < Kd; kt += GBK) {
    #pragma unroll
    for (int i = 0; i < 2; i++) {
      int idx4 = tid + i * 256;
      // A tile: 128 rows x 16 k  (float4 along k)
      int am = idx4 >> 2, ak4 = idx4 & 3;
      const float4 av = *(const float4*)(Ab + (size_t)am * Kd + kt + ak4 * 4);
      As2[ak4*4 + 0][am] = dup2(av.x);
      As2[ak4*4 + 1][am] = dup2(av.y);
      As2[ak4*4 + 2][am] = dup2(av.z);
      As2[ak4*4 + 3][am] = dup2(av.w);
      // B tile: 16 k x 128 n  (float4 along n, fully coalesced)
      int bk = idx4 >> 5, bn4 = idx4 & 31;
      const float4 bv = *(const float4*)(Bb + (size_t)(kt + bk) * N + bn4 * 4);
      *(float4*)&Bs[bk][bn4 * 4] = bv;
    }
    __syncthreads();

    #pragma unroll
    for (int kk = 0; kk < GBK; kk++) {
      unsigned long long a8[8];
      #pragma unroll
      for (int j = 0; j < 8; j++) a8[j] = As2[kk][r0 + j];
      const ulonglong2* bp = (const ulonglong2*)&Bs[kk][c0];
      ulonglong2 b01 = bp[0];
      ulonglong2 b23 = bp[1];
      unsigned long long b4[4] = { b01.x, b01.y, b23.x, b23.y };
      #pragma unroll
      for (int r = 0; r < 8; r++) {
        #pragma unroll
        for (int c = 0; c < 4; c++) ffma2(acc[r][c], a8[r], b4[c]);
      }
    }
    __syncthreads();
  }

  #pragma unroll
  for (int r = 0; r < 8; r++) {
    float outv[8];
    #pragma unroll
    for (int c = 0; c < 4; c++) {
      float2 f = unpk2(acc[r][c]);
      outv[c*2]   = f.x;
      outv[c*2+1] = f.y;
    }
    float* Cp = C + (size_t)(tileM + r0 + r) * N + tileN + c0;
    *(float4*)(Cp)     = make_float4(outv[0], outv[1], outv[2], outv[3]);
    *(float4*)(Cp + 4) = make_float4(outv[4], outv[5], outv[6], outv[7]);
  }
}

// ---------------------------------------------------------------------------
// beta = sigmoid(x @ Wb): one block per row m, 64 threads = (4 parts x 16 heads)
// writes [B,H,T] layout for the scan.
// ---------------------------------------------------------------------------
__global__ void beta_kernel(const float* __restrict__ x, const float* __restrict__ Wb,
                            float* __restrict__ gb)
{
  const int m = blockIdx.x;
  const int tid = threadIdx.x;
  const int h = tid & 15, part = tid >> 4;
  __shared__ float sx[DD];
  for (int i = tid; i < DD/4; i += 64)
    *(float4*)&sx[i*4] = *(const float4*)&x[(size_t)m * DD + i*4];
  __syncthreads();
  float acc = 0.f;
  const int kbase = part * 256;
  for (int kk = 0; kk < 256; kk++)
    acc += sx[kbase + kk] * Wb[(size_t)(kbase + kk) * HH + h];
  __shared__ float red[64];
  red[tid] = acc;
  __syncthreads();
  if (tid < 16) {
    float s = red[tid] + red[tid+16] + red[tid+32] + red[tid+48];
    int b = m >> 11, t = m & (TT-1);
    gb[((size_t)b * HH + tid) * TT + t] = 1.f / (1.f + __expf(-s));
  }
}

// ---------------------------------------------------------------------------
// Causal depthwise conv (K=4) + SiLU (+ optional per-head L2 norm),
// transposes [M,D] -> [B,H,T,DH]. One block per (b,t), 256 threads x 4 channels.
// ---------------------------------------------------------------------------
template<bool NORM>
__global__ void conv_kernel(const float* __restrict__ X, const float* __restrict__ W,
                            float* __restrict__ Y)
{
  const int m = blockIdx.x;
  const int b = m >> 11, t = m & (TT-1);
  const int tid = threadIdx.x;
  const int c0 = tid * 4;

  float warr[4][4];
  #pragma unroll
  for (int j = 0; j < 4; j++) {
    float4 wv = *(const float4*)&W[(size_t)(c0 + j) * 4];
    warr[j][0] = wv.x; warr[j][1] = wv.y; warr[j][2] = wv.z; warr[j][3] = wv.w;
  }

  float acc[4] = {0.f, 0.f, 0.f, 0.f};
  #pragma unroll
  for (int i = 0; i < 4; i++) {
    int tt = t - 3 + i;
    if (tt >= 0) {
      float4 xv = *(const float4*)&X[((size_t)(b * TT + tt)) * DD + c0];
      acc[0] += warr[0][i] * xv.x;
      acc[1] += warr[1][i] * xv.y;
      acc[2] += warr[2][i] * xv.z;
      acc[3] += warr[3][i] * xv.w;
    }
  }
  float y[4];
  #pragma unroll
  for (int j = 0; j < 4; j++) {
    float s = 1.f / (1.f + __expf(-acc[j]));
    y[j] = acc[j] * s;
  }

  float scale = 1.f;
  if (NORM) {
    float ss = y[0]*y[0] + y[1]*y[1] + y[2]*y[2] + y[3]*y[3];
    #pragma unroll
    for (int off = 8; off > 0; off >>= 1)
      ss += __shfl_xor_sync(0xffffffffu, ss, off, 16);
    scale = rsqrtf(ss + 1e-6f);
  }

  const int h = tid >> 4;
  const int dh0 = (tid & 15) * 4;
  float4 outv = make_float4(y[0]*scale, y[1]*scale, y[2]*scale, y[3]*scale);
  *(float4*)&Y[(((size_t)(b * HH + h)) * TT + t) * DHH + dh0] = outv;
}

// ---------------------------------------------------------------------------
// Sequential delta-rule scan. One block per (b,h). 128 threads:
// v = tid&63 (column of S), half = tid>>6 (k rows [half*32, half*32+32)).
// S[32] in registers; k_t/q_t staged in double-buffered smem with one-step
// software prefetch; 2-way smem reduction for k^T S and q^T S.
// ---------------------------------------------------------------------------
__global__ __launch_bounds__(128, 1)
void scan_kernel(const float* __restrict__ gq, const float* __restrict__ gk,
                 const float* __restrict__ gv, const float* __restrict__ gb,
                 float* __restrict__ go)
{
  const int bh = blockIdx.x;
  const float* q  = gq + (size_t)bh * TT * DHH;
  const float* k  = gk + (size_t)bh * TT * DHH;
  const float* v  = gv + (size_t)bh * TT * DHH;
  const float* be = gb + (size_t)bh * TT;
  float* o        = go + (size_t)bh * TT * DHH;

  const int tid  = threadIdx.x;
  const int vcol = tid & 63;
  const int half = tid >> 6;
  const int kofs = half * 32;

  float S[32];
  #pragma unroll
  for (int i = 0; i < 32; i++) S[i] = 0.f;

  __shared__ __align__(16) float sk[2][64];
  __shared__ __align__(16) float sq[2][64];
  __shared__ float redA[2][64];
  __shared__ float redB[2][64];

  // prologue: stage t=0
  if (tid < 64) sk[0][tid] = k[tid];
  else          sq[0][tid - 64] = q[tid - 64];
  float vt = v[vcol];
  float bt = be[0];
  __syncthreads();

  float kn = 0.f, qn = 0.f, vn = 0.f, bn = 0.f;

  for (int t = 0; t < TT; t++) {
    const int cur = t & 1, nxt = cur ^ 1;
    // prefetch step t+1 (hidden under compute)
    if (t + 1 < TT) {
      if (tid < 64) kn = k[(size_t)(t + 1) * DHH + tid];
      else          qn = q[(size_t)(t + 1) * DHH + tid - 64];
      vn = v[(size_t)(t + 1) * DHH + vcol];
      bn = be[t + 1];
    }

    const float* skc = sk[cur];
    const float* sqc = sq[cur];

    float kreg[32];
    float acc = 0.f;
    #pragma unroll
    for (int i = 0; i < 32; i++) {
      kreg[i] = skc[kofs + i];
      acc += kreg[i] * S[i];
    }
    redA[half][vcol] = acc;
    __syncthreads();

    float kS = redA[0][vcol] + redA[1][vcol];
    float u = bt * (vt - kS);

    float oacc = 0.f;
    #pragma unroll
    for (int i = 0; i < 32; i++) {
      S[i] += kreg[i] * u;
      oacc += sqc[kofs + i] * S[i];
    }
    redB[half][vcol] = oacc;
    __syncthreads();

    if (half == 0) o[(size_t)t * DHH + vcol] = redB[0][vcol] + redB[1][vcol];
    if (t + 1 < TT) {
      if (tid < 64) sk[nxt][tid] = kn;
      else          sq[nxt][tid - 64] = qn;
    }
    vt = vn; bt = bn;
    __syncthreads();
  }
}

// ---------------------------------------------------------------------------
// Per-head RMSNorm (mean over DH) * rms_g, transpose [B,H,T,DH] -> [M,D].
// ---------------------------------------------------------------------------
__global__ void rmsnorm_kernel(const float* __restrict__ O, const float* __restrict__ g,
                               float* __restrict__ Y)
{
  const int m = blockIdx.x;
  const int b = m >> 11, t = m & (TT-1);
  const int tid = threadIdx.x;
  const int h = tid >> 4;
  const int dh0 = (tid & 15) * 4;

  float4 ov = *(const float4*)&O[(((size_t)(b * HH + h)) * TT + t) * DHH + dh0];
  float ss = ov.x*ov.x + ov.y*ov.y + ov.z*ov.z + ov.w*ov.w;
  #pragma unroll
  for (int off = 8; off > 0; off >>= 1)
    ss += __shfl_xor_sync(0xffffffffu, ss, off, 16);
  float sc = rsqrtf(ss * (1.f / 64.f) + 1e-6f);
  float4 gv = *(const float4*)&g[dh0];
  float4 yv = make_float4(ov.x * sc * gv.x, ov.y * sc * gv.y,
                          ov.z * sc * gv.z, ov.w * sc * gv.w);
  *(float4*)&Y[(size_t)m * DD + tid * 4] = yv;
}

// ---------------------------------------------------------------------------
// Launch
// ---------------------------------------------------------------------------
extern "C" void kernel_launch(void* const* d_in, const int* in_sizes, int n_in,
                              void* d_out, int out_size)
{
  (void)in_sizes; (void)n_in; (void)out_size;
  const float* x  = (const float*)d_in[0];
  const float* Wq = (const float*)d_in[1];
  const float* Wk = (const float*)d_in[2];
  const float* Wv = (const float*)d_in[3];
  const float* Wb = (const float*)d_in[4];
  const float* cq = (const float*)d_in[5];
  const float* ck = (const float*)d_in[6];
  const float* cv = (const float*)d_in[7];
  const float* rg = (const float*)d_in[8];
  const float* Wo = (const float*)d_in[9];
  float* out = (float*)d_out;

  float *qc, *kc, *vc, *q, *k, *v, *beta, *o, *on;
  cudaGetSymbolAddress((void**)&qc,  g_qc);
  cudaGetSymbolAddress((void**)&kc,  g_kc);
  cudaGetSymbolAddress((void**)&vc,  g_vc);
  cudaGetSymbolAddress((void**)&q,   g_q);
  cudaGetSymbolAddress((void**)&k,   g_k);
  cudaGetSymbolAddress((void**)&v,   g_v);
  cudaGetSymbolAddress((void**)&beta, g_beta);
  cudaGetSymbolAddress((void**)&o,   g_o);
  cudaGetSymbolAddress((void**)&on,  g_on);

  dim3 gg(DD / GBN, MM / GBM);

  gemm_f32x2_kernel<<<gg, 256>>>(x, Wq, qc, MM, DD, DD);
  gemm_f32x2_kernel<<<gg, 256>>>(x, Wk, kc, MM, DD, DD);
  gemm_f32x2_kernel<<<gg, 256>>>(x, Wv, vc, MM, DD, DD);
  beta_kernel<<<MM, 64>>>(x, Wb, beta);
  conv_kernel<true ><<<MM, 256>>>(qc, cq, q);
  conv_kernel<true ><<<MM, 256>>>(kc, ck, k);
  conv_kernel<false><<<MM, 256>>>(vc, cv, v);
  scan_kernel<<<BB * HH, 128>>>(q, k, v, beta, o);
  rmsnorm_kernel<<<MM, 256>>>(o, rg, on);
  gemm_f32x2_kernel<<<gg, 256>>>(on, Wo, out, MM, DD, DD);
}

// round 4
// speedup vs baseline: 1.5865x; 1.5865x over previous
#include <cuda_runtime.h>
#include <cuda_bf16.h>
#include <cstdint>

// Problem constants
#define BB 2
#define TT 2048
#define DD 1024
#define HH 16
#define DHH 64
#define MM (BB*TT)          // 4096 rows

// ---------------------------------------------------------------------------
// Scratch (device globals: no runtime allocation allowed)
// ---------------------------------------------------------------------------
__device__ float g_qc[MM*DD];          // x@Wq (pre-conv), [M,D]
__device__ float g_kc[MM*DD];
__device__ float g_vc[MM*DD];
__device__ float g_q [MM*DD];          // post conv/silu/l2norm, [B,H,T,DH]
__device__ float g_k [MM*DD];
__device__ float g_v [MM*DD];
__device__ float g_beta[BB*HH*TT];     // [B,H,T]
__device__ float g_o [MM*DD];          // scan output, [B,H,T,DH]

// bf16 split operands for tensor-core GEMMs
__device__ __nv_bfloat16 g_xh[MM*DD];  // x hi, [M,K]
__device__ __nv_bfloat16 g_xl[MM*DD];  // x lo
__device__ __nv_bfloat16 g_oh[MM*DD];  // rmsnormed output hi, [M,K]
__device__ __nv_bfloat16 g_ol[MM*DD];
__device__ __nv_bfloat16 g_wh[4][DD*DD]; // W^T hi [N,K] for Wq,Wk,Wv,Wo
__device__ __nv_bfloat16 g_wl[4][DD*DD];

// ---------------------------------------------------------------------------
// f32x2 packed helpers (Blackwell FFMA2)
// ---------------------------------------------------------------------------
__device__ __forceinline__ unsigned long long dup2(float x){
  unsigned long long r;
  unsigned u = __float_as_uint(x);
  asm("mov.b64 %0, {%1, %1};" : "=l"(r) : "r"(u));
  return r;
}
__device__ __forceinline__ void ffma2(unsigned long long &c, unsigned long long a, unsigned long long b){
  asm("fma.rn.f32x2 %0, %1, %2, %0;" : "+l"(c) : "l"(a), "l"(b));
}
__device__ __forceinline__ float2 unpk2(unsigned long long p){
  unsigned lo, hi;
  asm("mov.b64 {%0, %1}, %2;" : "=r"(lo), "=r"(hi) : "l"(p));
  return make_float2(__uint_as_float(lo), __uint_as_float(hi));
}

// ---------------------------------------------------------------------------
// smem / cp.async / mma helpers (all base compute_103-legal: sm_80 era)
// ---------------------------------------------------------------------------
__device__ __forceinline__ uint32_t smem_u32(const void* p){
  uint32_t a;
  asm("{ .reg .u64 t; cvta.to.shared.u64 t, %1; cvt.u32.u64 %0, t; }" : "=r"(a) : "l"(p));
  return a;
}
__device__ __forceinline__ void cpasync16(uint32_t dst, const void* src){
  asm volatile("cp.async.cg.shared.global [%0], [%1], 16;" :: "r"(dst), "l"(src));
}
__device__ __forceinline__ void cpasync_commit(){
  asm volatile("cp.async.commit_group;" ::: "memory");
}
__device__ __forceinline__ void ldm4(uint32_t* r, uint32_t addr){
  asm volatile("ldmatrix.sync.aligned.m8n8.x4.shared.b16 {%0,%1,%2,%3}, [%4];"
               : "=r"(r[0]), "=r"(r[1]), "=r"(r[2]), "=r"(r[3]) : "r"(addr));
}
__device__ __forceinline__ void mma16816(float* d, const uint32_t* a, const uint32_t* b){
  asm volatile(
    "mma.sync.aligned.m16n8k16.row.col.f32.bf16.bf16.f32 "
    "{%0,%1,%2,%3}, {%4,%5,%6,%7}, {%8,%9}, {%0,%1,%2,%3};"
    : "+f"(d[0]), "+f"(d[1]), "+f"(d[2]), "+f"(d[3])
    : "r"(a[0]), "r"(a[1]), "r"(a[2]), "r"(a[3]), "r"(b[0]), "r"(b[1]));
}

// ---------------------------------------------------------------------------
// Tensor-pipe GEMM: C[M,1024] = (Ah+Al)[M,1024] @ (Bh+Bl)^T, B stored [N,K].
// 3-term bf16 split, fp32 accum. Tile 128x128, K-chunk 32, 2-stage cp.async.
// 8 warps = 2(M) x 4(N); warp tile 64x32 = 4 m-tiles x 4 n-tiles of m16n8.
// smem rows padded to 80B -> conflict-free ldmatrix.
// ---------------------------------------------------------------------------
#define GK   1024
#define KC   32
#define NCH  (GK/KC)           // 32 chunks
#define ROWB 80                // bytes per smem row (32 bf16 + 8 pad)
#define MATB (128*ROWB)        // 10240 B per matrix tile
#define STAGEB (4*MATB)        // Ah,Al,Bh,Bl = 40960
#define GEMM_SMEM (2*STAGEB)   // 81920

__global__ __launch_bounds__(256, 2)
void gemm_mma(const __nv_bfloat16* __restrict__ Ah, const __nv_bfloat16* __restrict__ Al,
              const __nv_bfloat16* __restrict__ Bh, const __nv_bfloat16* __restrict__ Bl,
              float* __restrict__ C)
{
  extern __shared__ char smem[];
  const uint32_t sb = smem_u32(smem);
  const int tid   = threadIdx.x;
  const int wid   = tid >> 5;
  const int lane  = tid & 31;
  const int warpM = wid & 1;       // 0..1
  const int warpN = wid >> 1;      // 0..3
  const int tileM = blockIdx.y * 128;
  const int tileN = blockIdx.x * 128;

  const __nv_bfloat16* gsrc[4] = {
    Ah + (size_t)tileM * GK, Al + (size_t)tileM * GK,
    Bh + (size_t)tileN * GK, Bl + (size_t)tileN * GK };

  // loader: 4 matrices x 128 rows x 4 chunks(16B) = 2048 chunks, 8 per thread
  auto load_stage = [&](int s, int kt){
    const uint32_t base = sb + s * STAGEB;
    #pragma unroll
    for (int i = 0; i < 8; i++){
      int cid = tid + i * 256;
      int mat = cid >> 9;
      int rem = cid & 511;
      int row = rem >> 2, ch = rem & 3;
      cpasync16(base + mat * MATB + row * ROWB + ch * 16,
                gsrc[mat] + (size_t)row * GK + kt + ch * 8);
    }
  };

  float acc[4][4][4];
  #pragma unroll
  for (int mt = 0; mt < 4; mt++)
    #pragma unroll
    for (int nt = 0; nt < 4; nt++)
      #pragma unroll
      for (int j = 0; j < 4; j++) acc[mt][nt][j] = 0.f;

  // per-lane ldmatrix address components
  const int aRow   = lane & 15;
  const int aKhalf = lane >> 4;                       // 0/1
  const uint32_t aOff = (uint32_t)(warpM*64 + aRow) * ROWB + aKhalf * 16;
  const int bRow   = (lane & 7) + ((lane >> 4) << 3); // 0..15
  const int bKhalf = (lane >> 3) & 1;
  const uint32_t bOff = (uint32_t)(warpN*32 + bRow) * ROWB + bKhalf * 16;

  load_stage(0, 0);  cpasync_commit();
  load_stage(1, KC); cpasync_commit();

  for (int c = 0; c < NCH; c++){
    if (c < NCH - 1) asm volatile("cp.async.wait_group 1;" ::: "memory");
    else             asm volatile("cp.async.wait_group 0;" ::: "memory");
    __syncthreads();

    const uint32_t sbuf = sb + (c & 1) * STAGEB;
    #pragma unroll
    for (int ks = 0; ks < 2; ks++){
      const uint32_t koff = ks * 32;
      uint32_t ah[4][4], bh[2][4], bl[2][4];
      #pragma unroll
      for (int mt = 0; mt < 4; mt++)
        ldm4(ah[mt], sbuf + 0*MATB + aOff + mt*16*ROWB + koff);
      #pragma unroll
      for (int p = 0; p < 2; p++)
        ldm4(bh[p], sbuf + 2*MATB + bOff + p*16*ROWB + koff);
      #pragma unroll
      for (int mt = 0; mt < 4; mt++)
        #pragma unroll
        for (int nt = 0; nt < 4; nt++)
          mma16816(acc[mt][nt], ah[mt], &bh[nt>>1][(nt&1)*2]);
      #pragma unroll
      for (int p = 0; p < 2; p++)
        ldm4(bl[p], sbuf + 3*MATB + bOff + p*16*ROWB + koff);
      #pragma unroll
      for (int mt = 0; mt < 4; mt++)
        #pragma unroll
        for (int nt = 0; nt < 4; nt++)
          mma16816(acc[mt][nt], ah[mt], &bl[nt>>1][(nt&1)*2]);
      #pragma unroll
      for (int mt = 0; mt < 4; mt++){
        uint32_t al_[4];
        ldm4(al_, sbuf + 1*MATB + aOff + mt*16*ROWB + koff);
        #pragma unroll
        for (int nt = 0; nt < 4; nt++)
          mma16816(acc[mt][nt], al_, &bh[nt>>1][(nt&1)*2]);
      }
    }
    __syncthreads();
    if (c + 2 < NCH){ load_stage(c & 1, (c + 2) * KC); cpasync_commit(); }
  }

  // epilogue
  const int rBase = tileM + warpM*64 + (lane >> 2);
  const int cBase = tileN + warpN*32 + (lane & 3) * 2;
  #pragma unroll
  for (int mt = 0; mt < 4; mt++){
    #pragma unroll
    for (int nt = 0; nt < 4; nt++){
      float* p0 = C + (size_t)(rBase + mt*16)     * GK + cBase + nt*8;
      float* p1 = C + (size_t)(rBase + mt*16 + 8) * GK + cBase + nt*8;
      *(float2*)p0 = make_float2(acc[mt][nt][0], acc[mt][nt][1]);
      *(float2*)p1 = make_float2(acc[mt][nt][2], acc[mt][nt][3]);
    }
  }
}

// ---------------------------------------------------------------------------
// fp32 -> (hi, lo) bf16 split, same layout
// ---------------------------------------------------------------------------
__global__ void split_kernel(const float* __restrict__ X,
                             __nv_bfloat16* __restrict__ H, __nv_bfloat16* __restrict__ L)
{
  int i = (blockIdx.x * 256 + threadIdx.x) * 4;
  float4 xv = *(const float4*)(X + i);
  float xs[4] = {xv.x, xv.y, xv.z, xv.w};
  __nv_bfloat16 h[4], l[4];
  #pragma unroll
  for (int j = 0; j < 4; j++){
    h[j] = __float2bfloat16_rn(xs[j]);
    l[j] = __float2bfloat16_rn(xs[j] - __bfloat162float(h[j]));
  }
  *(__nv_bfloat162*)(H + i)     = __nv_bfloat162(h[0], h[1]);
  *(__nv_bfloat162*)(H + i + 2) = __nv_bfloat162(h[2], h[3]);
  *(__nv_bfloat162*)(L + i)     = __nv_bfloat162(l[0], l[1]);
  *(__nv_bfloat162*)(L + i + 2) = __nv_bfloat162(l[2], l[3]);
}

// ---------------------------------------------------------------------------
// Weight transpose + bf16 split: W[K,N] fp32 -> Wt hi/lo [N,K] bf16
// ---------------------------------------------------------------------------
__global__ void wsplit_kernel(const float* __restrict__ W,
                              __nv_bfloat16* __restrict__ TH, __nv_bfloat16* __restrict__ TL)
{
  __shared__ float tile[32][33];
  const int n0 = blockIdx.x * 32, k0 = blockIdx.y * 32;
  const int tx = threadIdx.x, ty = threadIdx.y;
  #pragma unroll
  for (int i = 0; i < 4; i++)
    tile[ty + i*8][tx] = W[(size_t)(k0 + ty + i*8) * DD + n0 + tx];
  __syncthreads();
  #pragma unroll
  for (int i = 0; i < 4; i++){
    float v = tile[tx][ty + i*8];
    __nv_bfloat16 h = __float2bfloat16_rn(v);
    __nv_bfloat16 l = __float2bfloat16_rn(v - __bfloat162float(h));
    size_t idx = (size_t)(n0 + ty + i*8) * DD + k0 + tx;
    TH[idx] = h; TL[idx] = l;
  }
}

// ---------------------------------------------------------------------------
// beta = sigmoid(x @ Wb)
// ---------------------------------------------------------------------------
__global__ void beta_kernel(const float* __restrict__ x, const float* __restrict__ Wb,
                            float* __restrict__ gb)
{
  const int m = blockIdx.x;
  const int tid = threadIdx.x;
  const int h = tid & 15, part = tid >> 4;
  __shared__ float sx[DD];
  for (int i = tid; i < DD/4; i += 64)
    *(float4*)&sx[i*4] = *(const float4*)&x[(size_t)m * DD + i*4];
  __syncthreads();
  float acc = 0.f;
  const int kbase = part * 256;
  for (int kk = 0; kk < 256; kk++)
    acc += sx[kbase + kk] * Wb[(size_t)(kbase + kk) * HH + h];
  __shared__ float red[64];
  red[tid] = acc;
  __syncthreads();
  if (tid < 16) {
    float s = red[tid] + red[tid+16] + red[tid+32] + red[tid+48];
    int b = m >> 11, t = m & (TT-1);
    gb[((size_t)b * HH + tid) * TT + t] = 1.f / (1.f + __expf(-s));
  }
}

// ---------------------------------------------------------------------------
// Causal depthwise conv (K=4) + SiLU (+ optional L2 norm), [M,D] -> [B,H,T,DH]
// ---------------------------------------------------------------------------
template<bool NORM>
__global__ void conv_kernel(const float* __restrict__ X, const float* __restrict__ W,
                            float* __restrict__ Y)
{
  const int m = blockIdx.x;
  const int b = m >> 11, t = m & (TT-1);
  const int tid = threadIdx.x;
  const int c0 = tid * 4;

  float warr[4][4];
  #pragma unroll
  for (int j = 0; j < 4; j++) {
    float4 wv = *(const float4*)&W[(size_t)(c0 + j) * 4];
    warr[j][0] = wv.x; warr[j][1] = wv.y; warr[j][2] = wv.z; warr[j][3] = wv.w;
  }
  float acc[4] = {0.f, 0.f, 0.f, 0.f};
  #pragma unroll
  for (int i = 0; i < 4; i++) {
    int tt = t - 3 + i;
    if (tt >= 0) {
      float4 xv = *(const float4*)&X[((size_t)(b * TT + tt)) * DD + c0];
      acc[0] += warr[0][i] * xv.x;
      acc[1] += warr[1][i] * xv.y;
      acc[2] += warr[2][i] * xv.z;
      acc[3] += warr[3][i] * xv.w;
    }
  }
  float y[4];
  #pragma unroll
  for (int j = 0; j < 4; j++) {
    float s = 1.f / (1.f + __expf(-acc[j]));
    y[j] = acc[j] * s;
  }
  float scale = 1.f;
  if (NORM) {
    float ss = y[0]*y[0] + y[1]*y[1] + y[2]*y[2] + y[3]*y[3];
    #pragma unroll
    for (int off = 8; off > 0; off >>= 1)
      ss += __shfl_xor_sync(0xffffffffu, ss, off, 16);
    scale = rsqrtf(ss + 1e-6f);
  }
  const int h = tid >> 4;
  const int dh0 = (tid & 15) * 4;
  *(float4*)&Y[(((size_t)(b * HH + h)) * TT + t) * DHH + dh0] =
      make_float4(y[0]*scale, y[1]*scale, y[2]*scale, y[3]*scale);
}

// ---------------------------------------------------------------------------
// Sequential delta-rule scan. One block per (b,h). 64 threads, thread v owns
// S[:,v] packed as 32 f32x2 pairs over k. k/q broadcast from double-buffered
// smem; no cross-thread reductions; ONE barrier per step.
// ---------------------------------------------------------------------------
__global__ __launch_bounds__(64, 1)
void scan_kernel(const float* __restrict__ gq, const float* __restrict__ gk,
                 const float* __restrict__ gv, const float* __restrict__ gb,
                 float* __restrict__ go)
{
  const int bh = blockIdx.x;
  const float* q  = gq + (size_t)bh * TT * DHH;
  const float* k  = gk + (size_t)bh * TT * DHH;
  const float* v  = gv + (size_t)bh * TT * DHH;
  const float* be = gb + (size_t)bh * TT;
  float* o        = go + (size_t)bh * TT * DHH;

  const int tid = threadIdx.x;   // = v column

  unsigned long long S2[32];
  #pragma unroll
  for (int i = 0; i < 32; i++) S2[i] = 0ull;

  __shared__ __align__(16) float skq[2][128];  // [0:64)=k_t, [64:128)=q_t

  skq[0][tid]      = k[tid];
  skq[0][64 + tid] = q[tid];
  float vt = v[tid];
  float bt = be[0];
  __syncthreads();

  for (int t = 0; t < TT; t++) {
    const int cur = t & 1, nxt = cur ^ 1;
    float kn = 0.f, qn = 0.f, vn = 0.f, bn = 0.f;
    if (t + 1 < TT) {
      kn = k[(size_t)(t + 1) * DHH + tid];
      qn = q[(size_t)(t + 1) * DHH + tid];
      vn = v[(size_t)(t + 1) * DHH + tid];
      bn = be[t + 1];
    }

    const ulonglong2* kp = (const ulonglong2*)&skq[cur][0];
    const ulonglong2* qp = (const ulonglong2*)&skq[cur][64];

    // kS = k_t . S[:,v]  (4-way split accumulators)
    unsigned long long a0 = 0ull, a1 = 0ull, a2 = 0ull, a3 = 0ull;
    #pragma unroll
    for (int i = 0; i < 8; i++) {
      ulonglong2 k1 = kp[2*i], k2 = kp[2*i + 1];
      ffma2(a0, k1.x, S2[4*i]);
      ffma2(a1, k1.y, S2[4*i + 1]);
      ffma2(a2, k2.x, S2[4*i + 2]);
      ffma2(a3, k2.y, S2[4*i + 3]);
    }
    float2 f0 = unpk2(a0), f1 = unpk2(a1), f2 = unpk2(a2), f3 = unpk2(a3);
    float kS = (f0.x + f0.y) + (f1.x + f1.y) + (f2.x + f2.y) + (f3.x + f3.y);
    float u = bt * (vt - kS);
    unsigned long long u2 = dup2(u);

    // S += k u ; o = q . S
    unsigned long long o0 = 0ull, o1 = 0ull, o2 = 0ull, o3 = 0ull;
    #pragma unroll
    for (int i = 0; i < 8; i++) {
      ulonglong2 k1 = kp[2*i], k2 = kp[2*i + 1];
      ulonglong2 q1 = qp[2*i], q2 = qp[2*i + 1];
      ffma2(S2[4*i],     k1.x, u2);  ffma2(o0, q1.x, S2[4*i]);
      ffma2(S2[4*i + 1], k1.y, u2);  ffma2(o1, q1.y, S2[4*i + 1]);
      ffma2(S2[4*i + 2], k2.x, u2);  ffma2(o2, q2.x, S2[4*i + 2]);
      ffma2(S2[4*i + 3], k2.y, u2);  ffma2(o3, q2.y, S2[4*i + 3]);
    }
    float2 g0 = unpk2(o0), g1 = unpk2(o1), g2 = unpk2(o2), g3 = unpk2(o3);
    o[(size_t)t * DHH + tid] = (g0.x + g0.y) + (g1.x + g1.y) + (g2.x + g2.y) + (g3.x + g3.y);

    if (t + 1 < TT) {
      skq[nxt][tid]      = kn;
      skq[nxt][64 + tid] = qn;
    }
    vt = vn; bt = bn;
    __syncthreads();
  }
}

// ---------------------------------------------------------------------------
// Per-head RMSNorm * rms_g, transpose [B,H,T,DH] -> [M,D], bf16 hi/lo split out
// ---------------------------------------------------------------------------
__global__ void rmsnorm_kernel(const float* __restrict__ O, const float* __restrict__ g,
                               __nv_bfloat16* __restrict__ YH, __nv_bfloat16* __restrict__ YL)
{
  const int m = blockIdx.x;
  const int b = m >> 11, t = m & (TT-1);
  const int tid = threadIdx.x;
  const int h = tid >> 4;
  const int dh0 = (tid & 15) * 4;

  float4 ov = *(const float4*)&O[(((size_t)(b * HH + h)) * TT + t) * DHH + dh0];
  float ss = ov.x*ov.x + ov.y*ov.y + ov.z*ov.z + ov.w*ov.w;
  #pragma unroll
  for (int off = 8; off > 0; off >>= 1)
    ss += __shfl_xor_sync(0xffffffffu, ss, off, 16);
  float sc = rsqrtf(ss * (1.f / 64.f) + 1e-6f);
  float4 gv = *(const float4*)&g[dh0];
  float ys[4] = { ov.x * sc * gv.x, ov.y * sc * gv.y, ov.z * sc * gv.z, ov.w * sc * gv.w };
  __nv_bfloat16 hh[4], ll[4];
  #pragma unroll
  for (int j = 0; j < 4; j++){
    hh[j] = __float2bfloat16_rn(ys[j]);
    ll[j] = __float2bfloat16_rn(ys[j] - __bfloat162float(hh[j]));
  }
  size_t base = (size_t)m * DD + tid * 4;
  *(__nv_bfloat162*)(YH + base)     = __nv_bfloat162(hh[0], hh[1]);
  *(__nv_bfloat162*)(YH + base + 2) = __nv_bfloat162(hh[2], hh[3]);
  *(__nv_bfloat162*)(YL + base)     = __nv_bfloat162(ll[0], ll[1]);
  *(__nv_bfloat162*)(YL + base + 2) = __nv_bfloat162(ll[2], ll[3]);
}

// ---------------------------------------------------------------------------
// Launch
// ---------------------------------------------------------------------------
extern "C" void kernel_launch(void* const* d_in, const int* in_sizes, int n_in,
                              void* d_out, int out_size)
{
  (void)in_sizes; (void)n_in; (void)out_size;
  const float* x  = (const float*)d_in[0];
  const float* Wq = (const float*)d_in[1];
  const float* Wk = (const float*)d_in[2];
  const float* Wv = (const float*)d_in[3];
  const float* Wb = (const float*)d_in[4];
  const float* cq = (const float*)d_in[5];
  const float* ck = (const float*)d_in[6];
  const float* cv = (const float*)d_in[7];
  const float* rg = (const float*)d_in[8];
  const float* Wo = (const float*)d_in[9];
  float* out = (float*)d_out;

  float *qc, *kc, *vc, *q, *k, *v, *beta, *o;
  __nv_bfloat16 *xh, *xl, *oh, *ol, *wh, *wl;
  cudaGetSymbolAddress((void**)&qc,  g_qc);
  cudaGetSymbolAddress((void**)&kc,  g_kc);
  cudaGetSymbolAddress((void**)&vc,  g_vc);
  cudaGetSymbolAddress((void**)&q,   g_q);
  cudaGetSymbolAddress((void**)&k,   g_k);
  cudaGetSymbolAddress((void**)&v,   g_v);
  cudaGetSymbolAddress((void**)&beta, g_beta);
  cudaGetSymbolAddress((void**)&o,   g_o);
  cudaGetSymbolAddress((void**)&xh,  g_xh);
  cudaGetSymbolAddress((void**)&xl,  g_xl);
  cudaGetSymbolAddress((void**)&oh,  g_oh);
  cudaGetSymbolAddress((void**)&ol,  g_ol);
  cudaGetSymbolAddress((void**)&wh,  g_wh);
  cudaGetSymbolAddress((void**)&wl,  g_wl);

  cudaFuncSetAttribute(gemm_mma, cudaFuncAttributeMaxDynamicSharedMemorySize, GEMM_SMEM);

  const size_t WSZ = (size_t)DD * DD;
  dim3 wgrid(32, 32), wblk(32, 8);
  dim3 ggrid(DD / 128, MM / 128);

  split_kernel<<<MM * DD / 1024, 256>>>(x, xh, xl);
  wsplit_kernel<<<wgrid, wblk>>>(Wq, wh + 0*WSZ, wl + 0*WSZ);
  wsplit_kernel<<<wgrid, wblk>>>(Wk, wh + 1*WSZ, wl + 1*WSZ);
  wsplit_kernel<<<wgrid, wblk>>>(Wv, wh + 2*WSZ, wl + 2*WSZ);
  wsplit_kernel<<<wgrid, wblk>>>(Wo, wh + 3*WSZ, wl + 3*WSZ);

  gemm_mma<<<ggrid, 256, GEMM_SMEM>>>(xh, xl, wh + 0*WSZ, wl + 0*WSZ, qc);
  gemm_mma<<<ggrid, 256, GEMM_SMEM>>>(xh, xl, wh + 1*WSZ, wl + 1*WSZ, kc);
  gemm_mma<<<ggrid, 256, GEMM_SMEM>>>(xh, xl, wh + 2*WSZ, wl + 2*WSZ, vc);

  beta_kernel<<<MM, 64>>>(x, Wb, beta);
  conv_kernel<true ><<<MM, 256>>>(qc, cq, q);
  conv_kernel<true ><<<MM, 256>>>(kc, ck, k);
  conv_kernel<false><<<MM, 256>>>(vc, cv, v);

  scan_kernel<<<BB * HH, 64>>>(q, k, v, beta, o);

  rmsnorm_kernel<<<MM, 256>>>(o, rg, oh, ol);
  gemm_mma<<<ggrid, 256, GEMM_SMEM>>>(oh, ol, wh + 3*WSZ, wl + 3*WSZ, out);
}